// round 13
// baseline (speedup 1.0000x reference)
#include <cuda_runtime.h>
#include <cuda_fp16.h>

// Packed fp32x2 FMA (Blackwell): d = a*b + d on both 32-bit halves.
__device__ __forceinline__ void fma2(unsigned long long& d,
                                     unsigned long long a,
                                     unsigned long long b) {
    asm("fma.rn.f32x2 %0, %1, %2, %0;" : "+l"(d) : "l"(a), "l"(b));
}
__device__ __forceinline__ unsigned long long pack2(float x, float y) {
    unsigned long long r;
    asm("mov.b64 %0, {%1, %2};" : "=l"(r) : "f"(x), "f"(y));
    return r;
}
__device__ __forceinline__ float2 unpack2(unsigned long long u) {
    float2 r;
    asm("mov.b64 {%0, %1}, %2;" : "=f"(r.x), "=f"(r.y) : "l"(u));
    return r;
}
// Bit-casts half2 <-> u32 (the __half2_as_uint intrinsic does not exist).
__device__ __forceinline__ unsigned h2_to_u32(__half2 h) {
    unsigned u;
    asm("mov.b32 %0, %1;" : "=r"(u) : "r"(*reinterpret_cast<unsigned*>(&h)));
    return u;
}
__device__ __forceinline__ __half2 u32_to_h2(unsigned u) {
    __half2 h;
    *reinterpret_cast<unsigned*>(&h) = u;
    return h;
}

// 128 threads = 4 warps/block. Each warp handles TWO vertices (half-warp each).
// R11 core (offset-pair packing + software pipelining) with FP16 WEIGHT STORAGE:
// w0..w7 are stored as 4x half2 (16B -> one LDS.128 instead of two), w8 stays
// fp32 (LDS.32). This halves the dominant L1 return-bandwidth term (weight
// broadcast 576B -> ~320B per vertex per k). Math remains fp32: halves are
// converted back with H2F before the FFMA2s. Dominant weights are O(0.1-1)
// (fp16 rel err <= 4.9e-4); the e^{-10 d^2} tail below fp16 subnormal range is
// normwise negligible.
//
// Per k per warp: 1 LDS.128 + 1 LDS.32 (weights) + 4 H2F.F32x2 + 4 g-dups
//                 + 16 FFMA2 + 4 FFMA. Features: 1 LDG.128 per lane per k.

static constexpr int KROW    = 8;              // floats per k row (16B halfs + w8 + pad)
static constexpr int HSTRIDE = 32 * KROW + 4;  // +16B: shifts the second half-warp's
                                               // broadcast reads by 4 banks

__global__ void __launch_bounds__(128, 6)
softpixel_kernel(const float* __restrict__ coords,   // [V,4]
                 const float* __restrict__ feats,    // [V,64]
                 const int*   __restrict__ nidx,     // [V,32]
                 const float* __restrict__ lsp,      // [1]
                 float*       __restrict__ out,      // [V,576]
                 int V)
{
    __shared__ __align__(16) float wsm[4][2 * HSTRIDE];   // ~8.3 KB/block

    const int warp = threadIdx.x >> 5;
    const int lane = threadIdx.x & 31;
    const int half = lane >> 4;        // which vertex of the pair
    const int l    = lane & 15;

    const int vraw = blockIdx.x * 8 + warp * 2 + half;
    const int v    = vraw < V ? vraw : V - 1;   // clamp: full-warp participation

    const float ls = __ldg(lsp);
    const float a  = -10.0f * ls;      // ACCUMULATE_KNN_EXPONENT
    const float s  = 1.0f / 32.0f;     // fold mean-over-K into weights

    float* wv = &wsm[warp][half * HSTRIDE];

    // ---------------- Phase A: weights (w0..w7 fp16-packed, w8 fp32) --------
    const float4 cv = *reinterpret_cast<const float4*>(coords + 4 * v);

    #pragma unroll
    for (int t = 0; t < 2; ++t) {
        const int k  = l + 16 * t;
        const int nb = nidx[v * 32 + k];
        const float4 cn = *reinterpret_cast<const float4*>(coords + 4 * nb);
        const float d0 = cv.x - cn.x;
        const float d1 = cv.y - cn.y;
        const float d2 = cv.z - cn.z;
        const float d3 = cv.w - cn.w;
        const float base = d0*d0 + d1*d1 + d2*d2 + d3*d3;
        const float b1 = base + 1.0f;  // ||o||^2 = 1 for the 8 axis offsets

        // Offset order from SoftPixelCNN.create_offsets('onlyaxes', D=4, sub=3):
        // 0:(0,0,0,0) 1:(0,-1,0,0) 2:(-1,0,0,0) 3:(0,0,-1,0) 4:(0,0,0,-1)
        // 5:(0,0,0,+1) 6:(0,0,+1,0) 7:(+1,0,0,0) 8:(0,+1,0,0)
        const float w0 = __expf(a * base) * s;
        const float w1 = __expf(a * (b1 - 2.0f * d1)) * s;
        const float w2 = __expf(a * (b1 - 2.0f * d0)) * s;
        const float w3 = __expf(a * (b1 - 2.0f * d2)) * s;
        const float w4 = __expf(a * (b1 - 2.0f * d3)) * s;
        const float w5 = __expf(a * (b1 + 2.0f * d3)) * s;
        const float w6 = __expf(a * (b1 + 2.0f * d2)) * s;
        const float w7 = __expf(a * (b1 + 2.0f * d0)) * s;
        const float w8 = __expf(a * (b1 + 2.0f * d1)) * s;

        uint4 hw;
        hw.x = h2_to_u32(__floats2half2_rn(w0, w1));
        hw.y = h2_to_u32(__floats2half2_rn(w2, w3));
        hw.z = h2_to_u32(__floats2half2_rn(w4, w5));
        hw.w = h2_to_u32(__floats2half2_rn(w6, w7));
        *reinterpret_cast<uint4*>(wv + k * KROW) = hw;   // 16B, aligned
        wv[k * KROW + 4] = w8;                           // fp32
    }
    __syncwarp();

    // ---------------- Phase B: pipelined accumulate (offset-pair packing) ---
    // acc[op][f] = packed { out[2*op][f], out[2*op+1][f] }
    unsigned long long acc[4][4];
    float acc8[4];
    #pragma unroll
    for (int op = 0; op < 4; ++op)
        #pragma unroll
        for (int f = 0; f < 4; ++f) acc[op][f] = 0ull;
    #pragma unroll
    for (int f = 0; f < 4; ++f) acc8[f] = 0.0f;

    const int fofs = 4 * l;            // this lane's 4-feature slice
    const int* nrow = nidx + v * 32;

    // Prologue: load chunk 0
    int4 nb4 = *reinterpret_cast<const int4*>(nrow);
    float4 g[4];
    g[0] = *reinterpret_cast<const float4*>(feats + nb4.x * 64 + fofs);
    g[1] = *reinterpret_cast<const float4*>(feats + nb4.y * 64 + fofs);
    g[2] = *reinterpret_cast<const float4*>(feats + nb4.z * 64 + fofs);
    g[3] = *reinterpret_cast<const float4*>(feats + nb4.w * 64 + fofs);

    #pragma unroll
    for (int c = 0; c < 8; ++c) {
        const int k0 = c * 4;

        // Prefetch chunk c+1 (indices then features) before computing chunk c.
        int4 nb4n;
        float4 gn[4];
        if (c < 7) {
            nb4n = *reinterpret_cast<const int4*>(nrow + k0 + 4);
            gn[0] = *reinterpret_cast<const float4*>(feats + nb4n.x * 64 + fofs);
            gn[1] = *reinterpret_cast<const float4*>(feats + nb4n.y * 64 + fofs);
            gn[2] = *reinterpret_cast<const float4*>(feats + nb4n.z * 64 + fofs);
            gn[3] = *reinterpret_cast<const float4*>(feats + nb4n.w * 64 + fofs);
        }

        #pragma unroll
        for (int j = 0; j < 4; ++j) {
            const int k = k0 + j;
            const uint4 hw = *reinterpret_cast<const uint4*>(wv + k * KROW);
            const float w8 = wv[k * KROW + 4];

            const float2 f01 = __half22float2(u32_to_h2(hw.x));
            const float2 f23 = __half22float2(u32_to_h2(hw.y));
            const float2 f45 = __half22float2(u32_to_h2(hw.z));
            const float2 f67 = __half22float2(u32_to_h2(hw.w));

            const unsigned long long w01 = pack2(f01.x, f01.y);
            const unsigned long long w23 = pack2(f23.x, f23.y);
            const unsigned long long w45 = pack2(f45.x, f45.y);
            const unsigned long long w67 = pack2(f67.x, f67.y);

            const unsigned long long gd0 = pack2(g[j].x, g[j].x);
            const unsigned long long gd1 = pack2(g[j].y, g[j].y);
            const unsigned long long gd2 = pack2(g[j].z, g[j].z);
            const unsigned long long gd3 = pack2(g[j].w, g[j].w);

            fma2(acc[0][0], w01, gd0); fma2(acc[0][1], w01, gd1);
            fma2(acc[0][2], w01, gd2); fma2(acc[0][3], w01, gd3);
            fma2(acc[1][0], w23, gd0); fma2(acc[1][1], w23, gd1);
            fma2(acc[1][2], w23, gd2); fma2(acc[1][3], w23, gd3);
            fma2(acc[2][0], w45, gd0); fma2(acc[2][1], w45, gd1);
            fma2(acc[2][2], w45, gd2); fma2(acc[2][3], w45, gd3);
            fma2(acc[3][0], w67, gd0); fma2(acc[3][1], w67, gd1);
            fma2(acc[3][2], w67, gd2); fma2(acc[3][3], w67, gd3);

            acc8[0] = fmaf(w8, g[j].x, acc8[0]);
            acc8[1] = fmaf(w8, g[j].y, acc8[1]);
            acc8[2] = fmaf(w8, g[j].z, acc8[2]);
            acc8[3] = fmaf(w8, g[j].w, acc8[3]);
        }

        // Rotate buffers (register renaming after full unroll — no MOVs)
        if (c < 7) {
            nb4 = nb4n;
            g[0] = gn[0]; g[1] = gn[1]; g[2] = gn[2]; g[3] = gn[3];
        }
    }

    // ---------------- Epilogue: unpack offset-pairs, vector stores ----------
    float* orow = out + (long long)v * 576 + fofs;
    #pragma unroll
    for (int op = 0; op < 4; ++op) {
        const float2 p0 = unpack2(acc[op][0]);
        const float2 p1 = unpack2(acc[op][1]);
        const float2 p2 = unpack2(acc[op][2]);
        const float2 p3 = unpack2(acc[op][3]);
        *reinterpret_cast<float4*>(orow + (2*op    ) * 64) =
            make_float4(p0.x, p1.x, p2.x, p3.x);
        *reinterpret_cast<float4*>(orow + (2*op + 1) * 64) =
            make_float4(p0.y, p1.y, p2.y, p3.y);
    }
    *reinterpret_cast<float4*>(orow + 8 * 64) =
        make_float4(acc8[0], acc8[1], acc8[2], acc8[3]);
}

extern "C" void kernel_launch(void* const* d_in, const int* in_sizes, int n_in,
                              void* d_out, int out_size) {
    const float* coords = (const float*)d_in[0];   // [V,4]
    const float* feats  = (const float*)d_in[1];   // [V,64]
    // d_in[2] = distsq — unused on the inference path (stop_gradient EMA input)
    const int*   nidx   = (const int*)d_in[3];     // [V,32]
    const float* lsp    = (const float*)d_in[4];   // [1]
    float* out = (float*)d_out;

    const int V = in_sizes[0] / 4;
    const int blocks = (V + 7) / 8;                // 8 vertices per 128-thread block
    softpixel_kernel<<<blocks, 128>>>(coords, feats, nidx, lsp, out, V);
}

// round 14
// speedup vs baseline: 1.0217x; 1.0217x over previous
#include <cuda_runtime.h>
#include <cuda_fp16.h>

// Packed fp32x2 FMA (Blackwell): d = a*b + d on both 32-bit halves.
__device__ __forceinline__ void fma2(unsigned long long& d,
                                     unsigned long long a,
                                     unsigned long long b) {
    asm("fma.rn.f32x2 %0, %1, %2, %0;" : "+l"(d) : "l"(a), "l"(b));
}
__device__ __forceinline__ unsigned long long pack2(float x, float y) {
    unsigned long long r;
    asm("mov.b64 %0, {%1, %2};" : "=l"(r) : "f"(x), "f"(y));
    return r;
}
__device__ __forceinline__ float2 unpack2(unsigned long long u) {
    float2 r;
    asm("mov.b64 {%0, %1}, %2;" : "=f"(r.x), "=f"(r.y) : "l"(u));
    return r;
}
// Bit-casts half2 <-> u32 (no __half2_as_uint intrinsic exists).
__device__ __forceinline__ unsigned h2_to_u32(__half2 h) {
    unsigned u;
    asm("mov.b32 %0, %1;" : "=r"(u) : "r"(*reinterpret_cast<unsigned*>(&h)));
    return u;
}
__device__ __forceinline__ __half2 u32_to_h2(unsigned u) {
    __half2 h;
    *reinterpret_cast<unsigned*>(&h) = u;
    return h;
}

// 128 threads = 4 warps/block. Each warp handles TWO vertices (half-warp each).
// R13 core (fp16 weight storage, offset-pair packing, feature chunk prefetch)
// + WEIGHT SOFTWARE PIPELINING: k+1's raw weight registers (uint4 + w8) are
// prefetched during k's FMA block, so the LDS(29cyc) latency — previously an
// exposed per-k serial chain LDS->F2F->pack->FFMA — is hidden. F2F latency is
// covered by the 20-FMA body of the same k.
//
// Per k per warp: 1 LDS.128 + 1 LDS.32 (weights, prefetched) + H2F converts
//                 + 4 g-dups + 16 FFMA2 + 4 FFMA. Features: 1 LDG.128/lane/k,
//                 prefetched one 4-k chunk ahead.

static constexpr int KROW    = 8;              // floats per k row (16B halfs + w8 + pad)
static constexpr int HSTRIDE = 32 * KROW + 4;  // +16B: shifts the second half-warp's
                                               // broadcast reads by 4 banks

__global__ void __launch_bounds__(128, 5)
softpixel_kernel(const float* __restrict__ coords,   // [V,4]
                 const float* __restrict__ feats,    // [V,64]
                 const int*   __restrict__ nidx,     // [V,32]
                 const float* __restrict__ lsp,      // [1]
                 float*       __restrict__ out,      // [V,576]
                 int V)
{
    __shared__ __align__(16) float wsm[4][2 * HSTRIDE];   // ~8.3 KB/block

    const int warp = threadIdx.x >> 5;
    const int lane = threadIdx.x & 31;
    const int half = lane >> 4;        // which vertex of the pair
    const int l    = lane & 15;

    const int vraw = blockIdx.x * 8 + warp * 2 + half;
    const int v    = vraw < V ? vraw : V - 1;   // clamp: full-warp participation

    const float ls = __ldg(lsp);
    const float a  = -10.0f * ls;      // ACCUMULATE_KNN_EXPONENT
    const float s  = 1.0f / 32.0f;     // fold mean-over-K into weights

    float* wv = &wsm[warp][half * HSTRIDE];

    // ---------------- Phase A: weights (w0..w7 fp16-packed, w8 fp32) --------
    const float4 cv = *reinterpret_cast<const float4*>(coords + 4 * v);

    #pragma unroll
    for (int t = 0; t < 2; ++t) {
        const int k  = l + 16 * t;
        const int nb = nidx[v * 32 + k];
        const float4 cn = *reinterpret_cast<const float4*>(coords + 4 * nb);
        const float d0 = cv.x - cn.x;
        const float d1 = cv.y - cn.y;
        const float d2 = cv.z - cn.z;
        const float d3 = cv.w - cn.w;
        const float base = d0*d0 + d1*d1 + d2*d2 + d3*d3;
        const float b1 = base + 1.0f;  // ||o||^2 = 1 for the 8 axis offsets

        // Offset order from SoftPixelCNN.create_offsets('onlyaxes', D=4, sub=3):
        // 0:(0,0,0,0) 1:(0,-1,0,0) 2:(-1,0,0,0) 3:(0,0,-1,0) 4:(0,0,0,-1)
        // 5:(0,0,0,+1) 6:(0,0,+1,0) 7:(+1,0,0,0) 8:(0,+1,0,0)
        const float w0 = __expf(a * base) * s;
        const float w1 = __expf(a * (b1 - 2.0f * d1)) * s;
        const float w2 = __expf(a * (b1 - 2.0f * d0)) * s;
        const float w3 = __expf(a * (b1 - 2.0f * d2)) * s;
        const float w4 = __expf(a * (b1 - 2.0f * d3)) * s;
        const float w5 = __expf(a * (b1 + 2.0f * d3)) * s;
        const float w6 = __expf(a * (b1 + 2.0f * d2)) * s;
        const float w7 = __expf(a * (b1 + 2.0f * d0)) * s;
        const float w8 = __expf(a * (b1 + 2.0f * d1)) * s;

        uint4 hw;
        hw.x = h2_to_u32(__floats2half2_rn(w0, w1));
        hw.y = h2_to_u32(__floats2half2_rn(w2, w3));
        hw.z = h2_to_u32(__floats2half2_rn(w4, w5));
        hw.w = h2_to_u32(__floats2half2_rn(w6, w7));
        *reinterpret_cast<uint4*>(wv + k * KROW) = hw;   // 16B, aligned
        wv[k * KROW + 4] = w8;                           // fp32
    }
    __syncwarp();

    // ---------------- Phase B: doubly-pipelined accumulate ------------------
    // acc[op][f] = packed { out[2*op][f], out[2*op+1][f] }
    unsigned long long acc[4][4];
    float acc8[4];
    #pragma unroll
    for (int op = 0; op < 4; ++op)
        #pragma unroll
        for (int f = 0; f < 4; ++f) acc[op][f] = 0ull;
    #pragma unroll
    for (int f = 0; f < 4; ++f) acc8[f] = 0.0f;

    const int fofs = 4 * l;            // this lane's 4-feature slice
    const int* nrow = nidx + v * 32;

    // Prologue: feature chunk 0 + weight row k=0
    int4 nb4 = *reinterpret_cast<const int4*>(nrow);
    float4 g[4];
    g[0] = *reinterpret_cast<const float4*>(feats + nb4.x * 64 + fofs);
    g[1] = *reinterpret_cast<const float4*>(feats + nb4.y * 64 + fofs);
    g[2] = *reinterpret_cast<const float4*>(feats + nb4.z * 64 + fofs);
    g[3] = *reinterpret_cast<const float4*>(feats + nb4.w * 64 + fofs);

    uint4 hwc = *reinterpret_cast<const uint4*>(wv);
    float w8c = wv[4];

    #pragma unroll
    for (int c = 0; c < 8; ++c) {
        const int k0 = c * 4;

        // Prefetch feature chunk c+1 before computing chunk c.
        int4 nb4n;
        float4 gn[4];
        if (c < 7) {
            nb4n = *reinterpret_cast<const int4*>(nrow + k0 + 4);
            gn[0] = *reinterpret_cast<const float4*>(feats + nb4n.x * 64 + fofs);
            gn[1] = *reinterpret_cast<const float4*>(feats + nb4n.y * 64 + fofs);
            gn[2] = *reinterpret_cast<const float4*>(feats + nb4n.z * 64 + fofs);
            gn[3] = *reinterpret_cast<const float4*>(feats + nb4n.w * 64 + fofs);
        }

        #pragma unroll
        for (int j = 0; j < 4; ++j) {
            const int k = k0 + j;

            // Prefetch weight row k+1 (raw) before using row k.
            uint4 hwn;
            float w8n;
            if (k < 31) {
                hwn = *reinterpret_cast<const uint4*>(wv + (k + 1) * KROW);
                w8n = wv[(k + 1) * KROW + 4];
            }

            const float2 f01 = __half22float2(u32_to_h2(hwc.x));
            const float2 f23 = __half22float2(u32_to_h2(hwc.y));
            const float2 f45 = __half22float2(u32_to_h2(hwc.z));
            const float2 f67 = __half22float2(u32_to_h2(hwc.w));

            const unsigned long long w01 = pack2(f01.x, f01.y);
            const unsigned long long w23 = pack2(f23.x, f23.y);
            const unsigned long long w45 = pack2(f45.x, f45.y);
            const unsigned long long w67 = pack2(f67.x, f67.y);

            const unsigned long long gd0 = pack2(g[j].x, g[j].x);
            const unsigned long long gd1 = pack2(g[j].y, g[j].y);
            const unsigned long long gd2 = pack2(g[j].z, g[j].z);
            const unsigned long long gd3 = pack2(g[j].w, g[j].w);

            fma2(acc[0][0], w01, gd0); fma2(acc[0][1], w01, gd1);
            fma2(acc[0][2], w01, gd2); fma2(acc[0][3], w01, gd3);
            fma2(acc[1][0], w23, gd0); fma2(acc[1][1], w23, gd1);
            fma2(acc[1][2], w23, gd2); fma2(acc[1][3], w23, gd3);
            fma2(acc[2][0], w45, gd0); fma2(acc[2][1], w45, gd1);
            fma2(acc[2][2], w45, gd2); fma2(acc[2][3], w45, gd3);
            fma2(acc[3][0], w67, gd0); fma2(acc[3][1], w67, gd1);
            fma2(acc[3][2], w67, gd2); fma2(acc[3][3], w67, gd3);

            acc8[0] = fmaf(w8c, g[j].x, acc8[0]);
            acc8[1] = fmaf(w8c, g[j].y, acc8[1]);
            acc8[2] = fmaf(w8c, g[j].z, acc8[2]);
            acc8[3] = fmaf(w8c, g[j].w, acc8[3]);

            if (k < 31) { hwc = hwn; w8c = w8n; }   // rename after full unroll
        }

        if (c < 7) {
            nb4 = nb4n;
            g[0] = gn[0]; g[1] = gn[1]; g[2] = gn[2]; g[3] = gn[3];
        }
    }

    // ---------------- Epilogue: unpack offset-pairs, vector stores ----------
    float* orow = out + (long long)v * 576 + fofs;
    #pragma unroll
    for (int op = 0; op < 4; ++op) {
        const float2 p0 = unpack2(acc[op][0]);
        const float2 p1 = unpack2(acc[op][1]);
        const float2 p2 = unpack2(acc[op][2]);
        const float2 p3 = unpack2(acc[op][3]);
        *reinterpret_cast<float4*>(orow + (2*op    ) * 64) =
            make_float4(p0.x, p1.x, p2.x, p3.x);
        *reinterpret_cast<float4*>(orow + (2*op + 1) * 64) =
            make_float4(p0.y, p1.y, p2.y, p3.y);
    }
    *reinterpret_cast<float4*>(orow + 8 * 64) =
        make_float4(acc8[0], acc8[1], acc8[2], acc8[3]);
}

extern "C" void kernel_launch(void* const* d_in, const int* in_sizes, int n_in,
                              void* d_out, int out_size) {
    const float* coords = (const float*)d_in[0];   // [V,4]
    const float* feats  = (const float*)d_in[1];   // [V,64]
    // d_in[2] = distsq — unused on the inference path (stop_gradient EMA input)
    const int*   nidx   = (const int*)d_in[3];     // [V,32]
    const float* lsp    = (const float*)d_in[4];   // [1]
    float* out = (float*)d_out;

    const int V = in_sizes[0] / 4;
    const int blocks = (V + 7) / 8;                // 8 vertices per 128-thread block
    softpixel_kernel<<<blocks, 128>>>(coords, feats, nidx, lsp, out, V);
}